// round 9
// baseline (speedup 1.0000x reference)
#include <cuda_runtime.h>

#define N_NODES 300000
#define DIM 128
#define KNBR 5
#define EPS_LN 1e-5f
#define BLOCK 64
#define NTHREADS 256
#define NTILES ((N_NODES + BLOCK - 1) / BLOCK)
#define PAD 68      // stride (floats) of k-major transposed tiles
#define TQS 132     // stride of row-major Q buffer
#define WCH 32      // weight chunk rows (k) per pipeline stage

typedef unsigned long long ull;

// ---------------- global scratch ----------------
__device__ float g_Kp1[(size_t)N_NODES * DIM];
__device__ float g_Vp1[(size_t)N_NODES * DIM];
__device__ float g_Kp2[(size_t)N_NODES * DIM];
__device__ float g_Vp2[(size_t)N_NODES * DIM];
__device__ float g_rowsum[N_NODES];

// ---------------- f32x2 helpers ----------------
__device__ __forceinline__ ull f2x2(float lo, float hi) {
    ull r;
    asm("mov.b64 %0, {%1, %2};" : "=l"(r) : "f"(lo), "f"(hi));
    return r;
}
__device__ __forceinline__ void ffma2(ull& d, ull a, ull b) {
    asm("fma.rn.f32x2 %0, %1, %2, %0;" : "+l"(d) : "l"(a), "l"(b));
}
__device__ __forceinline__ void unpk(ull v, float& lo, float& hi) {
    asm("mov.b64 {%0, %1}, %2;" : "=f"(lo), "=f"(hi) : "l"(v));
}
__device__ __forceinline__ unsigned sptr(const void* p) {
    return (unsigned)__cvta_generic_to_shared(p);
}
__device__ __forceinline__ void cp16(unsigned saddr, const void* g) {
    asm volatile("cp.async.cg.shared.global [%0], [%1], 16;" :: "r"(saddr), "l"(g));
}
__device__ __forceinline__ void cp_commit() {
    asm volatile("cp.async.commit_group;" ::: "memory");
}
__device__ __forceinline__ void cp_waitall() {
    asm volatile("cp.async.wait_group 0;" ::: "memory");
}

// ---------------- shared memory layouts ----------------
struct SmemMain {
    float XT[DIM * PAD];   // residual stream, k-major          (34816 B)
    float W0[WCH * DIM];   // weight chunk ping                 (16384 B)
    float W1[WCH * DIM];   // weight chunk pong                 (16384 B)
    float S[DIM * PAD];    // scratch: Tq | AT | U | H | F      (34816 B)
    int   nidx[BLOCK * KNBR];
    int   nmask[BLOCK * KNBR];
};                          // ~102.5 KB -> 2 CTAs/SM
struct SmemPre {
    float XT[DIM * PAD];
    float W0[WCH * DIM];
    float W1[WCH * DIM];
};                          // ~66 KB

// ---------------- W chunk loader (cp.async, 32 rows x 128 cols) ----------------
__device__ __forceinline__ void issue32(const float* __restrict__ Wg,
                                        int row0, int col0, int ncols,
                                        float* __restrict__ Ws) {
    int tid = threadIdx.x;
    #pragma unroll
    for (int i = tid; i < 1024; i += NTHREADS) {   // 1024 float4
        int r  = i >> 5;
        int c4 = (i & 31) << 2;
        cp16(sptr(Ws + r * DIM + c4),
             Wg + (size_t)(row0 + r) * ncols + col0 + c4);
    }
}

__device__ __forceinline__ void zacc16(ull acc[16]) {
    #pragma unroll
    for (int i = 0; i < 16; ++i) acc[i] = 0ull;
}

// Warp tile 32x32, thread tile 8 rows x 4 cols; K=WCH chunk.
__device__ __forceinline__ void gemm32(const float* __restrict__ A,
                                       const float* __restrict__ Ws,
                                       int rbase, int cbase, ull acc[16]) {
    const float* ap = A + rbase;
    const float* wp = Ws + cbase;
    #pragma unroll 4
    for (int k = 0; k < WCH; ++k) {
        ulonglong2 a01 = *(const ulonglong2*)(ap);      // rows rbase..+3
        ulonglong2 a23 = *(const ulonglong2*)(ap + 4);  // rows rbase+4..+7
        float4 w4v = *(const float4*)(wp);
        ull wx = f2x2(w4v.x, w4v.x);
        ull wy = f2x2(w4v.y, w4v.y);
        ull wz = f2x2(w4v.z, w4v.z);
        ull ww = f2x2(w4v.w, w4v.w);
        ffma2(acc[0],  a01.x, wx); ffma2(acc[1],  a01.y, wx);
        ffma2(acc[2],  a23.x, wx); ffma2(acc[3],  a23.y, wx);
        ffma2(acc[4],  a01.x, wy); ffma2(acc[5],  a01.y, wy);
        ffma2(acc[6],  a23.x, wy); ffma2(acc[7],  a23.y, wy);
        ffma2(acc[8],  a01.x, wz); ffma2(acc[9],  a01.y, wz);
        ffma2(acc[10], a23.x, wz); ffma2(acc[11], a23.y, wz);
        ffma2(acc[12], a01.x, ww); ffma2(acc[13], a01.y, ww);
        ffma2(acc[14], a23.x, ww); ffma2(acc[15], a23.y, ww);
        ap += PAD; wp += DIM;
    }
}

// Pipelined K=128 gemm: 4 chunks of WCH rows, ping-pong W0/W1.
// If preloaded, chunk0 was already issued into W0 (after a full barrier).
__device__ __forceinline__ void gemm128_pipe(const float* __restrict__ A,
                                             const float* __restrict__ Wg,
                                             int col0, int ncols,
                                             float* __restrict__ B0,
                                             float* __restrict__ B1,
                                             int rbase, int cbase, ull acc[16],
                                             bool preloaded) {
    if (!preloaded) {
        __syncthreads();                 // all warps done with prior W/S reads
        issue32(Wg, 0, col0, ncols, B0);
        cp_commit();
    }
    #pragma unroll
    for (int c = 0; c < 4; ++c) {
        cp_waitall();
        __syncthreads();                 // chunk c visible; prior-buf readers done
        if (c < 3) {
            issue32(Wg, (c + 1) * WCH, col0, ncols, (c & 1) ? B0 : B1);
            cp_commit();
        }
        gemm32(A + c * WCH * PAD, (c & 1) ? B1 : B0, rbase, cbase, acc);
    }
}

// store acc to k-major buffer with bias (+optional relu)
__device__ __forceinline__ void store_t(float* __restrict__ Dst,
                                        const float* __restrict__ bias,
                                        bool relu, int rbase, int cbase,
                                        const ull acc[16]) {
    #pragma unroll
    for (int c = 0; c < 4; ++c) {
        float bv = bias[cbase + c];
        #pragma unroll
        for (int rp = 0; rp < 4; ++rp) {
            float lo, hi;
            unpk(acc[c * 4 + rp], lo, hi);
            lo += bv; hi += bv;
            if (relu) { lo = fmaxf(lo, 0.f); hi = fmaxf(hi, 0.f); }
            *(float2*)(Dst + (size_t)(cbase + c) * PAD + rbase + rp * 2) =
                make_float2(lo, hi);
        }
    }
}

// LN: XT = LN(XT + UT)*gamma + beta. 2 units per thread.
__device__ __forceinline__ void ln_t(float* __restrict__ XT,
                                     const float* __restrict__ UT,
                                     const float* __restrict__ gamma,
                                     const float* __restrict__ beta) {
    int tid = threadIdx.x;
    #pragma unroll
    for (int u = 0; u < 2; ++u) {
        int idx  = tid + u * NTHREADS;
        int node = idx >> 3;
        int h    = idx & 7;
        float v[16];
        float sum = 0.f;
        #pragma unroll
        for (int i = 0; i < 16; ++i) {
            int e = h + 8 * i;
            v[i] = XT[e * PAD + node] + UT[e * PAD + node];
            sum += v[i];
        }
        sum += __shfl_xor_sync(0xffffffffu, sum, 1);
        sum += __shfl_xor_sync(0xffffffffu, sum, 2);
        sum += __shfl_xor_sync(0xffffffffu, sum, 4);
        float m = sum * (1.f / 128.f);
        float sq = 0.f;
        #pragma unroll
        for (int i = 0; i < 16; ++i) { float d = v[i] - m; sq = fmaf(d, d, sq); }
        sq += __shfl_xor_sync(0xffffffffu, sq, 1);
        sq += __shfl_xor_sync(0xffffffffu, sq, 2);
        sq += __shfl_xor_sync(0xffffffffu, sq, 4);
        float inv = rsqrtf(sq * (1.f / 128.f) + EPS_LN);
        #pragma unroll
        for (int i = 0; i < 16; ++i) {
            int e = h + 8 * i;
            XT[e * PAD + node] = (v[i] - m) * inv * gamma[e] + beta[e];
        }
    }
}

// ---------------- one transformer layer ----------------
__device__ void run_layer(SmemMain* s, int base,
                          const float* wq, const float* wo, const float* bo,
                          const float* wa, const float* ba,
                          const float* wb, const float* bb,
                          const float* ga, const float* bea,
                          const float* gb, const float* beb,
                          const float* __restrict__ Kp,
                          const float* __restrict__ Vp) {
    int tid  = threadIdx.x;
    int lane = tid & 31, warp = tid >> 5;
    int rbase = ((warp & 1) * 4 + (lane >> 3)) * 8;    // 0..56
    int cbase = (warp >> 1) * 32 + (lane & 7) * 4;     // 0..124
    float* Tq = s->S;          // row-major 64 x TQS
    ull acc[16];

    // ---- 1. Q = X @ wq -> Tq ----
    zacc16(acc);
    gemm128_pipe(s->XT, wq, 0, DIM, s->W0, s->W1, rbase, cbase, acc, false);
    #pragma unroll
    for (int c = 0; c < 4; ++c)
        #pragma unroll
        for (int rp = 0; rp < 4; ++rp) {
            float lo, hi;
            unpk(acc[c * 4 + rp], lo, hi);
            Tq[(rbase + rp * 2)     * TQS + cbase + c] = lo;
            Tq[(rbase + rp * 2 + 1) * TQS + cbase + c] = hi;
        }
    __syncthreads();   // Tq visible; all warps past Q-gemm

    // prefetch wo chunk 0 while attention gathers run
    issue32(wo, 0, 0, DIM, s->W0);
    cp_commit();

    // ---- 2. attention: 2 (node,head) units per thread ----
    float4 o2[2][4];
    #pragma unroll
    for (int u = 0; u < 2; ++u) {
        #pragma unroll
        for (int t = 0; t < 4; ++t) o2[u][t] = make_float4(0.f, 0.f, 0.f, 0.f);
        int idx  = tid + u * NTHREADS;
        int node = idx >> 3;
        int h    = idx & 7;
        int g    = base + node;
        if (g < N_NODES) {
            const float* qs = Tq + node * TQS + h * 16;
            float q[16];
            #pragma unroll
            for (int t = 0; t < 4; ++t) {
                float4 q4 = *(const float4*)(qs + t * 4);
                q[4*t] = q4.x; q[4*t+1] = q4.y; q[4*t+2] = q4.z; q[4*t+3] = q4.w;
            }
            float dots[KNBR]; bool msk[KNBR];
            #pragma unroll
            for (int j = 0; j < KNBR; ++j) {
                int mflag = s->nmask[node * KNBR + j];
                msk[j] = (mflag != 0);
                if (mflag) { dots[j] = -1e30f; continue; }
                int nb = s->nidx[node * KNBR + j];
                const float4* kp = (const float4*)(Kp + (size_t)nb * DIM + h * 16);
                float d = 0.f;
                #pragma unroll
                for (int t = 0; t < 4; ++t) {
                    float4 k4 = kp[t];
                    d = fmaf(q[4*t+0], k4.x, d);
                    d = fmaf(q[4*t+1], k4.y, d);
                    d = fmaf(q[4*t+2], k4.z, d);
                    d = fmaf(q[4*t+3], k4.w, d);
                }
                dots[j] = d * 0.25f;
            }
            float mmax = -1e30f;
            #pragma unroll
            for (int j = 0; j < KNBR; ++j) mmax = fmaxf(mmax, dots[j]);
            float e[KNBR]; float ssum = 0.f;
            #pragma unroll
            for (int j = 0; j < KNBR; ++j) {
                e[j] = msk[j] ? 0.f : __expf(dots[j] - mmax);
                ssum += e[j];
            }
            float inv = 1.f / ssum;
            #pragma unroll
            for (int j = 0; j < KNBR; ++j) {
                if (!msk[j]) {
                    int nb = s->nidx[node * KNBR + j];
                    const float4* vp = (const float4*)(Vp + (size_t)nb * DIM + h * 16);
                    float a = e[j] * inv;
                    #pragma unroll
                    for (int t = 0; t < 4; ++t) {
                        float4 v4 = vp[t];
                        o2[u][t].x = fmaf(a, v4.x, o2[u][t].x);
                        o2[u][t].y = fmaf(a, v4.y, o2[u][t].y);
                        o2[u][t].z = fmaf(a, v4.z, o2[u][t].z);
                        o2[u][t].w = fmaf(a, v4.w, o2[u][t].w);
                    }
                }
            }
        }
    }
    __syncthreads();   // everyone finished reading Tq
    #pragma unroll
    for (int u = 0; u < 2; ++u) {
        int idx  = tid + u * NTHREADS;
        int node = idx >> 3;
        int h    = idx & 7;
        #pragma unroll
        for (int t = 0; t < 4; ++t) {
            int cc = h * 16 + t * 4;
            s->S[(cc + 0) * PAD + node] = o2[u][t].x;
            s->S[(cc + 1) * PAD + node] = o2[u][t].y;
            s->S[(cc + 2) * PAD + node] = o2[u][t].z;
            s->S[(cc + 3) * PAD + node] = o2[u][t].w;
        }
    }
    // AT stores become visible at the pipe's first internal barrier

    // ---- 3. U = attn @ wo + bo ----
    zacc16(acc);
    gemm128_pipe(s->S, wo, 0, DIM, s->W0, s->W1, rbase, cbase, acc, true);
    __syncthreads();                 // all done reading AT (S)
    store_t(s->S, bo, false, rbase, cbase, acc);   // U over AT
    issue32(wa, 0, 0, 256, s->W0);   // prefetch wa chunk0 during LN
    cp_commit();
    __syncthreads();                 // U visible

    // ---- 4. X = LN(X + U) ----
    ln_t(s->XT, s->S, ga, bea);
    // LN'd XT becomes visible at the pipe's first internal barrier

    // ---- 5/6. FFN: per output-half, H-half -> accF ----
    ull accF[16]; zacc16(accF);
    #pragma unroll
    for (int h = 0; h < 2; ++h) {
        zacc16(acc);
        gemm128_pipe(s->XT, wa, h * 128, 256, s->W0, s->W1, rbase, cbase, acc,
                     h == 0);
        __syncthreads();            // all warps past H-gemm; S readers (prev wb) done
        store_t(s->S, ba + h * 128, true, rbase, cbase, acc);  // H-half
        gemm128_pipe(s->S, wb + (size_t)h * 128 * DIM, 0, DIM,
                     s->W0, s->W1, rbase, cbase, accF, false);
    }
    __syncthreads();                // all done reading H (S)
    store_t(s->S, bb, false, rbase, cbase, accF);   // F
    __syncthreads();

    // ---- 7. X = LN(X + F) ----
    ln_t(s->XT, s->S, gb, beb);
    __syncthreads();
}

// ---------------- kernel 1: Kp/Vp projections + row sums ----------------
extern "C" __global__ void __launch_bounds__(NTHREADS, 3)
pre_kernel(const float* __restrict__ feat,
           const float* __restrict__ wk1, const float* __restrict__ wv1,
           const float* __restrict__ wk2, const float* __restrict__ wv2) {
    extern __shared__ char smem_raw[];
    SmemPre* s = (SmemPre*)smem_raw;
    int tid  = threadIdx.x;
    int base = blockIdx.x * BLOCK;

    #pragma unroll
    for (int i = tid; i < BLOCK * 32; i += NTHREADS) {
        int node = i >> 5;
        int k4   = (i & 31) << 2;
        int g    = base + node;
        float4 v = make_float4(0.f, 0.f, 0.f, 0.f);
        if (g < N_NODES) v = *(const float4*)(feat + (size_t)g * DIM + k4);
        s->XT[(k4 + 0) * PAD + node] = v.x;
        s->XT[(k4 + 1) * PAD + node] = v.y;
        s->XT[(k4 + 2) * PAD + node] = v.z;
        s->XT[(k4 + 3) * PAD + node] = v.w;
    }
    __syncthreads();

    {   // row sums (2 units per thread)
        #pragma unroll
        for (int u = 0; u < 2; ++u) {
            int idx  = tid + u * NTHREADS;
            int node = idx >> 3;
            int h    = idx & 7;
            float ssum = 0.f;
            #pragma unroll
            for (int i = 0; i < 16; ++i) ssum += s->XT[(h + 8 * i) * PAD + node];
            ssum += __shfl_xor_sync(0xffffffffu, ssum, 1);
            ssum += __shfl_xor_sync(0xffffffffu, ssum, 2);
            ssum += __shfl_xor_sync(0xffffffffu, ssum, 4);
            int g = base + node;
            if (h == 0 && g < N_NODES) g_rowsum[g] = ssum;
        }
    }

    int lane = tid & 31, warp = tid >> 5;
    int rbase = ((warp & 1) * 4 + (lane >> 3)) * 8;
    int cbase = (warp >> 1) * 32 + (lane & 7) * 4;
    const float* ws_in[4] = {wk1, wv1, wk2, wv2};
    float* outs[4] = {g_Kp1, g_Vp1, g_Kp2, g_Vp2};
    ull acc[16];
    #pragma unroll
    for (int w = 0; w < 4; ++w) {
        zacc16(acc);
        gemm128_pipe(s->XT, ws_in[w], 0, DIM, s->W0, s->W1, rbase, cbase, acc,
                     false);
        float* op = outs[w];
        #pragma unroll
        for (int rp = 0; rp < 4; ++rp) {
            float lo0, hi0, lo1, hi1, lo2, hi2, lo3, hi3;
            unpk(acc[0 * 4 + rp], lo0, hi0);
            unpk(acc[1 * 4 + rp], lo1, hi1);
            unpk(acc[2 * 4 + rp], lo2, hi2);
            unpk(acc[3 * 4 + rp], lo3, hi3);
            int g0 = base + rbase + rp * 2;
            if (g0 < N_NODES)
                *(float4*)(op + (size_t)g0 * DIM + cbase) = make_float4(lo0, lo1, lo2, lo3);
            if (g0 + 1 < N_NODES)
                *(float4*)(op + (size_t)(g0 + 1) * DIM + cbase) = make_float4(hi0, hi1, hi2, hi3);
        }
    }
}

// ---------------- kernel 2: fused 2-layer transformer + head ----------------
extern "C" __global__ void __launch_bounds__(NTHREADS, 2)
main_kernel(const float* __restrict__ feat,
            const int* __restrict__ nbr_idx,
            const int* __restrict__ nbr_valid,
            const float* wq1, const float* wo1, const float* bo1,
            const float* w1a, const float* b1a, const float* w1b, const float* b1b,
            const float* g1a, const float* be1a, const float* g1b, const float* be1b,
            const float* wq2, const float* wo2, const float* bo2,
            const float* w2a, const float* b2a, const float* w2b, const float* b2b,
            const float* g2a, const float* be2a, const float* g2b, const float* be2b,
            const float* w4, const float* b4,
            float* __restrict__ out) {
    extern __shared__ char smem_raw[];
    SmemMain* s = (SmemMain*)smem_raw;
    int tid  = threadIdx.x;
    int base = blockIdx.x * BLOCK;

    #pragma unroll
    for (int i = tid; i < BLOCK * 32; i += NTHREADS) {
        int node = i >> 5;
        int k4   = (i & 31) << 2;
        int g    = base + node;
        float4 v = make_float4(0.f, 0.f, 0.f, 0.f);
        if (g < N_NODES) v = *(const float4*)(feat + (size_t)g * DIM + k4);
        s->XT[(k4 + 0) * PAD + node] = v.x;
        s->XT[(k4 + 1) * PAD + node] = v.y;
        s->XT[(k4 + 2) * PAD + node] = v.z;
        s->XT[(k4 + 3) * PAD + node] = v.w;
    }
    for (int i = tid; i < BLOCK * KNBR; i += NTHREADS) {
        int node = i / KNBR;
        int j    = i - node * KNBR;
        int g    = base + node;
        int idx = 0, mflag = 1;
        if (g < N_NODES) {
            idx = nbr_idx[(size_t)g * KNBR + j];
            int valid = nbr_valid[(size_t)g * KNBR + j];   // nonzero = true
            mflag = (valid == 0) || (g_rowsum[idx] == 0.f);
        }
        s->nidx[i]  = idx;
        s->nmask[i] = mflag;
    }
    __syncthreads();

    run_layer(s, base, wq1, wo1, bo1, w1a, b1a, w1b, b1b,
              g1a, be1a, g1b, be1b, g_Kp1, g_Vp1);
    run_layer(s, base, wq2, wo2, bo2, w2a, b2a, w2b, b2b,
              g2a, be2a, g2b, be2b, g_Kp2, g_Vp2);

    // ---- head: out = tanh(X @ w4 + b4), w4: 128x64 (fits W0+W1) ----
    __syncthreads();
    {
        #pragma unroll
        for (int i = tid; i < 2048; i += NTHREADS) {   // 2048 float4
            int r  = i >> 4;
            int c4 = (i & 15) << 2;
            cp16(sptr(s->W0 + r * 64 + c4), w4 + r * 64 + c4);
        }
        cp_commit();
        cp_waitall();
    }
    __syncthreads();
    #pragma unroll
    for (int u = 0; u < 2; ++u) {
        int idx  = tid + u * NTHREADS;
        int node = idx >> 3;
        int c0   = (idx & 7) * 8;
        float acc8[8];
        #pragma unroll
        for (int c = 0; c < 8; ++c) acc8[c] = 0.f;
        #pragma unroll 4
        for (int kk = 0; kk < DIM; ++kk) {
            float a = s->XT[kk * PAD + node];
            float4 w0 = *(const float4*)(s->W0 + kk * 64 + c0);
            float4 w1 = *(const float4*)(s->W0 + kk * 64 + c0 + 4);
            acc8[0] = fmaf(a, w0.x, acc8[0]);
            acc8[1] = fmaf(a, w0.y, acc8[1]);
            acc8[2] = fmaf(a, w0.z, acc8[2]);
            acc8[3] = fmaf(a, w0.w, acc8[3]);
            acc8[4] = fmaf(a, w1.x, acc8[4]);
            acc8[5] = fmaf(a, w1.y, acc8[5]);
            acc8[6] = fmaf(a, w1.z, acc8[6]);
            acc8[7] = fmaf(a, w1.w, acc8[7]);
        }
        int g = base + node;
        if (g < N_NODES) {
            #pragma unroll
            for (int c = 0; c < 8; ++c)
                out[(size_t)g * 64 + c0 + c] = tanhf(acc8[c] + b4[c0 + c]);
        }
    }
}

// ---------------- host launch ----------------
extern "C" void kernel_launch(void* const* d_in, const int* in_sizes, int n_in,
                              void* d_out, int out_size) {
    const float* feat  = (const float*)d_in[0];
    const int* nbr_idx = (const int*)d_in[1];
    const int* nbr_val = (const int*)d_in[2];
    const float* wq1 = (const float*)d_in[3];
    const float* wk1 = (const float*)d_in[4];
    const float* wv1 = (const float*)d_in[5];
    const float* wo1 = (const float*)d_in[6];
    const float* bo1 = (const float*)d_in[7];
    const float* w1a = (const float*)d_in[8];
    const float* b1a = (const float*)d_in[9];
    const float* w1b = (const float*)d_in[10];
    const float* b1b = (const float*)d_in[11];
    const float* g1a = (const float*)d_in[12];
    const float* be1a = (const float*)d_in[13];
    const float* g1b = (const float*)d_in[14];
    const float* be1b = (const float*)d_in[15];
    const float* wq2 = (const float*)d_in[16];
    const float* wk2 = (const float*)d_in[17];
    const float* wv2 = (const float*)d_in[18];
    const float* wo2 = (const float*)d_in[19];
    const float* bo2 = (const float*)d_in[20];
    const float* w2a = (const float*)d_in[21];
    const float* b2a = (const float*)d_in[22];
    const float* w2b = (const float*)d_in[23];
    const float* b2b = (const float*)d_in[24];
    const float* g2a = (const float*)d_in[25];
    const float* be2a = (const float*)d_in[26];
    const float* g2b = (const float*)d_in[27];
    const float* be2b = (const float*)d_in[28];
    const float* w4 = (const float*)d_in[29];
    const float* b4 = (const float*)d_in[30];
    float* out = (float*)d_out;

    size_t smem_pre  = sizeof(SmemPre);
    size_t smem_main = sizeof(SmemMain);
    cudaFuncSetAttribute(pre_kernel,  cudaFuncAttributeMaxDynamicSharedMemorySize, (int)smem_pre);
    cudaFuncSetAttribute(main_kernel, cudaFuncAttributeMaxDynamicSharedMemorySize, (int)smem_main);

    pre_kernel<<<NTILES, NTHREADS, smem_pre>>>(feat, wk1, wv1, wk2, wv2);
    main_kernel<<<NTILES, NTHREADS, smem_main>>>(
        feat, nbr_idx, nbr_val,
        wq1, wo1, bo1, w1a, b1a, w1b, b1b, g1a, be1a, g1b, be1b,
        wq2, wo2, bo2, w2a, b2a, w2b, b2b, g2a, be2a, g2b, be2b,
        w4, b4, out);
}

// round 10
// speedup vs baseline: 1.0026x; 1.0026x over previous
#include <cuda_runtime.h>

#define N_NODES 300000
#define DIM 128
#define KNBR 5
#define EPS_LN 1e-5f
#define BLOCK 64
#define NTHREADS 256
#define NTILES ((N_NODES + BLOCK - 1) / BLOCK)
#define PAD 68      // stride (floats) of k-major transposed tiles
#define TQS 132     // stride of row-major Q buffer
#define WCH 32      // weight chunk rows (k) per pipeline stage

typedef unsigned long long ull;

// ---------------- global scratch ----------------
__device__ float g_Kp1[(size_t)N_NODES * DIM];
__device__ float g_Vp1[(size_t)N_NODES * DIM];
__device__ float g_Kp2[(size_t)N_NODES * DIM];
__device__ float g_Vp2[(size_t)N_NODES * DIM];
__device__ float g_rowsum[N_NODES];

// ---------------- f32x2 helpers ----------------
__device__ __forceinline__ ull f2x2(float lo, float hi) {
    ull r;
    asm("mov.b64 %0, {%1, %2};" : "=l"(r) : "f"(lo), "f"(hi));
    return r;
}
__device__ __forceinline__ void ffma2(ull& d, ull a, ull b) {
    asm("fma.rn.f32x2 %0, %1, %2, %0;" : "+l"(d) : "l"(a), "l"(b));
}
__device__ __forceinline__ void unpk(ull v, float& lo, float& hi) {
    asm("mov.b64 {%0, %1}, %2;" : "=f"(lo), "=f"(hi) : "l"(v));
}
__device__ __forceinline__ unsigned sptr(const void* p) {
    return (unsigned)__cvta_generic_to_shared(p);
}
__device__ __forceinline__ void cp16(unsigned saddr, const void* g) {
    asm volatile("cp.async.cg.shared.global [%0], [%1], 16;" :: "r"(saddr), "l"(g));
}
__device__ __forceinline__ void cp_commit() {
    asm volatile("cp.async.commit_group;" ::: "memory");
}
__device__ __forceinline__ void cp_waitall() {
    asm volatile("cp.async.wait_group 0;" ::: "memory");
}

// ---------------- shared memory layouts ----------------
struct SmemMain {
    float XT[DIM * PAD];   // residual stream, k-major          (34816 B)
    float W0[WCH * DIM];   // weight chunk ping                 (16384 B)
    float W1[WCH * DIM];   // weight chunk pong                 (16384 B)
    float S[DIM * PAD];    // scratch: Tq | AT | U | H | F      (34816 B)
    int   nidx[BLOCK * KNBR];
    int   nmask[BLOCK * KNBR];
};                          // ~102.5 KB -> 2 CTAs/SM
struct SmemPre {
    float XT[DIM * PAD];
    float W0[WCH * DIM];
    float W1[WCH * DIM];
};                          // ~66 KB

// ---------------- W chunk loader (cp.async, 32 rows x 128 cols) ----------------
__device__ __forceinline__ void issue32(const float* __restrict__ Wg,
                                        int row0, int col0, int ncols,
                                        float* __restrict__ Ws) {
    int tid = threadIdx.x;
    #pragma unroll
    for (int i = tid; i < 1024; i += NTHREADS) {   // 1024 float4
        int r  = i >> 5;
        int c4 = (i & 31) << 2;
        cp16(sptr(Ws + r * DIM + c4),
             Wg + (size_t)(row0 + r) * ncols + col0 + c4);
    }
}

__device__ __forceinline__ void zacc16(ull acc[16]) {
    #pragma unroll
    for (int i = 0; i < 16; ++i) acc[i] = 0ull;
}

// Warp tile 32x32, thread tile 8 rows x 4 cols; K=WCH chunk.
__device__ __forceinline__ void gemm32(const float* __restrict__ A,
                                       const float* __restrict__ Ws,
                                       int rbase, int cbase, ull acc[16]) {
    const float* ap = A + rbase;
    const float* wp = Ws + cbase;
    #pragma unroll 4
    for (int k = 0; k < WCH; ++k) {
        ulonglong2 a01 = *(const ulonglong2*)(ap);      // rows rbase..+3
        ulonglong2 a23 = *(const ulonglong2*)(ap + 4);  // rows rbase+4..+7
        float4 w4v = *(const float4*)(wp);
        ull wx = f2x2(w4v.x, w4v.x);
        ull wy = f2x2(w4v.y, w4v.y);
        ull wz = f2x2(w4v.z, w4v.z);
        ull ww = f2x2(w4v.w, w4v.w);
        ffma2(acc[0],  a01.x, wx); ffma2(acc[1],  a01.y, wx);
        ffma2(acc[2],  a23.x, wx); ffma2(acc[3],  a23.y, wx);
        ffma2(acc[4],  a01.x, wy); ffma2(acc[5],  a01.y, wy);
        ffma2(acc[6],  a23.x, wy); ffma2(acc[7],  a23.y, wy);
        ffma2(acc[8],  a01.x, wz); ffma2(acc[9],  a01.y, wz);
        ffma2(acc[10], a23.x, wz); ffma2(acc[11], a23.y, wz);
        ffma2(acc[12], a01.x, ww); ffma2(acc[13], a01.y, ww);
        ffma2(acc[14], a23.x, ww); ffma2(acc[15], a23.y, ww);
        ap += PAD; wp += DIM;
    }
}

// Pipelined K=128 gemm: 4 chunks of WCH rows, ping-pong W0/W1.
// If preloaded, chunk0 was already issued into W0 (after a full barrier).
__device__ __forceinline__ void gemm128_pipe(const float* __restrict__ A,
                                             const float* __restrict__ Wg,
                                             int col0, int ncols,
                                             float* __restrict__ B0,
                                             float* __restrict__ B1,
                                             int rbase, int cbase, ull acc[16],
                                             bool preloaded) {
    if (!preloaded) {
        __syncthreads();                 // all warps done with prior W/S reads
        issue32(Wg, 0, col0, ncols, B0);
        cp_commit();
    }
    #pragma unroll
    for (int c = 0; c < 4; ++c) {
        cp_waitall();
        __syncthreads();                 // chunk c visible; prior-buf readers done
        if (c < 3) {
            issue32(Wg, (c + 1) * WCH, col0, ncols, (c & 1) ? B0 : B1);
            cp_commit();
        }
        gemm32(A + c * WCH * PAD, (c & 1) ? B1 : B0, rbase, cbase, acc);
    }
}

// store acc to k-major buffer with bias (+optional relu)
__device__ __forceinline__ void store_t(float* __restrict__ Dst,
                                        const float* __restrict__ bias,
                                        bool relu, int rbase, int cbase,
                                        const ull acc[16]) {
    #pragma unroll
    for (int c = 0; c < 4; ++c) {
        float bv = bias[cbase + c];
        #pragma unroll
        for (int rp = 0; rp < 4; ++rp) {
            float lo, hi;
            unpk(acc[c * 4 + rp], lo, hi);
            lo += bv; hi += bv;
            if (relu) { lo = fmaxf(lo, 0.f); hi = fmaxf(hi, 0.f); }
            *(float2*)(Dst + (size_t)(cbase + c) * PAD + rbase + rp * 2) =
                make_float2(lo, hi);
        }
    }
}

// LN: XT = LN(XT + UT)*gamma + beta. 2 units per thread.
__device__ __forceinline__ void ln_t(float* __restrict__ XT,
                                     const float* __restrict__ UT,
                                     const float* __restrict__ gamma,
                                     const float* __restrict__ beta) {
    int tid = threadIdx.x;
    #pragma unroll
    for (int u = 0; u < 2; ++u) {
        int idx  = tid + u * NTHREADS;
        int node = idx >> 3;
        int h    = idx & 7;
        float v[16];
        float sum = 0.f;
        #pragma unroll
        for (int i = 0; i < 16; ++i) {
            int e = h + 8 * i;
            v[i] = XT[e * PAD + node] + UT[e * PAD + node];
            sum += v[i];
        }
        sum += __shfl_xor_sync(0xffffffffu, sum, 1);
        sum += __shfl_xor_sync(0xffffffffu, sum, 2);
        sum += __shfl_xor_sync(0xffffffffu, sum, 4);
        float m = sum * (1.f / 128.f);
        float sq = 0.f;
        #pragma unroll
        for (int i = 0; i < 16; ++i) { float d = v[i] - m; sq = fmaf(d, d, sq); }
        sq += __shfl_xor_sync(0xffffffffu, sq, 1);
        sq += __shfl_xor_sync(0xffffffffu, sq, 2);
        sq += __shfl_xor_sync(0xffffffffu, sq, 4);
        float inv = rsqrtf(sq * (1.f / 128.f) + EPS_LN);
        #pragma unroll
        for (int i = 0; i < 16; ++i) {
            int e = h + 8 * i;
            XT[e * PAD + node] = (v[i] - m) * inv * gamma[e] + beta[e];
        }
    }
}

// ---------------- one transformer layer ----------------
__device__ void run_layer(SmemMain* s, int base,
                          const float* wq, const float* wo, const float* bo,
                          const float* wa, const float* ba,
                          const float* wb, const float* bb,
                          const float* ga, const float* bea,
                          const float* gb, const float* beb,
                          const float* __restrict__ Kp,
                          const float* __restrict__ Vp) {
    int tid  = threadIdx.x;
    int lane = tid & 31, warp = tid >> 5;
    int rbase = ((warp & 1) * 4 + (lane >> 3)) * 8;    // 0..56
    int cbase = (warp >> 1) * 32 + (lane & 7) * 4;     // 0..124
    float* Tq = s->S;          // row-major 64 x TQS
    ull acc[16];

    // ---- 1. Q = X @ wq -> Tq ----
    zacc16(acc);
    gemm128_pipe(s->XT, wq, 0, DIM, s->W0, s->W1, rbase, cbase, acc, false);
    #pragma unroll
    for (int c = 0; c < 4; ++c)
        #pragma unroll
        for (int rp = 0; rp < 4; ++rp) {
            float lo, hi;
            unpk(acc[c * 4 + rp], lo, hi);
            Tq[(rbase + rp * 2)     * TQS + cbase + c] = lo;
            Tq[(rbase + rp * 2 + 1) * TQS + cbase + c] = hi;
        }
    __syncthreads();   // Tq visible; all warps past Q-gemm

    // prefetch wo chunk 0 while attention gathers run
    issue32(wo, 0, 0, DIM, s->W0);
    cp_commit();

    // ---- 2. attention: 2 (node,head) units per thread ----
    float4 o2[2][4];
    #pragma unroll
    for (int u = 0; u < 2; ++u) {
        #pragma unroll
        for (int t = 0; t < 4; ++t) o2[u][t] = make_float4(0.f, 0.f, 0.f, 0.f);
        int idx  = tid + u * NTHREADS;
        int node = idx >> 3;
        int h    = idx & 7;
        int g    = base + node;
        if (g < N_NODES) {
            const float* qs = Tq + node * TQS + h * 16;
            float q[16];
            #pragma unroll
            for (int t = 0; t < 4; ++t) {
                float4 q4 = *(const float4*)(qs + t * 4);
                q[4*t] = q4.x; q[4*t+1] = q4.y; q[4*t+2] = q4.z; q[4*t+3] = q4.w;
            }
            float dots[KNBR]; bool msk[KNBR];
            #pragma unroll
            for (int j = 0; j < KNBR; ++j) {
                int mflag = s->nmask[node * KNBR + j];
                msk[j] = (mflag != 0);
                if (mflag) { dots[j] = -1e30f; continue; }
                int nb = s->nidx[node * KNBR + j];
                const float4* kp = (const float4*)(Kp + (size_t)nb * DIM + h * 16);
                float d = 0.f;
                #pragma unroll
                for (int t = 0; t < 4; ++t) {
                    float4 k4 = kp[t];
                    d = fmaf(q[4*t+0], k4.x, d);
                    d = fmaf(q[4*t+1], k4.y, d);
                    d = fmaf(q[4*t+2], k4.z, d);
                    d = fmaf(q[4*t+3], k4.w, d);
                }
                dots[j] = d * 0.25f;
            }
            float mmax = -1e30f;
            #pragma unroll
            for (int j = 0; j < KNBR; ++j) mmax = fmaxf(mmax, dots[j]);
            float e[KNBR]; float ssum = 0.f;
            #pragma unroll
            for (int j = 0; j < KNBR; ++j) {
                e[j] = msk[j] ? 0.f : __expf(dots[j] - mmax);
                ssum += e[j];
            }
            float inv = 1.f / ssum;
            #pragma unroll
            for (int j = 0; j < KNBR; ++j) {
                if (!msk[j]) {
                    int nb = s->nidx[node * KNBR + j];
                    const float4* vp = (const float4*)(Vp + (size_t)nb * DIM + h * 16);
                    float a = e[j] * inv;
                    #pragma unroll
                    for (int t = 0; t < 4; ++t) {
                        float4 v4 = vp[t];
                        o2[u][t].x = fmaf(a, v4.x, o2[u][t].x);
                        o2[u][t].y = fmaf(a, v4.y, o2[u][t].y);
                        o2[u][t].z = fmaf(a, v4.z, o2[u][t].z);
                        o2[u][t].w = fmaf(a, v4.w, o2[u][t].w);
                    }
                }
            }
        }
    }
    __syncthreads();   // everyone finished reading Tq
    #pragma unroll
    for (int u = 0; u < 2; ++u) {
        int idx  = tid + u * NTHREADS;
        int node = idx >> 3;
        int h    = idx & 7;
        #pragma unroll
        for (int t = 0; t < 4; ++t) {
            int cc = h * 16 + t * 4;
            s->S[(cc + 0) * PAD + node] = o2[u][t].x;
            s->S[(cc + 1) * PAD + node] = o2[u][t].y;
            s->S[(cc + 2) * PAD + node] = o2[u][t].z;
            s->S[(cc + 3) * PAD + node] = o2[u][t].w;
        }
    }
    // AT stores become visible at the pipe's first internal barrier

    // ---- 3. U = attn @ wo + bo ----
    zacc16(acc);
    gemm128_pipe(s->S, wo, 0, DIM, s->W0, s->W1, rbase, cbase, acc, true);
    __syncthreads();                 // all done reading AT (S)
    store_t(s->S, bo, false, rbase, cbase, acc);   // U over AT
    issue32(wa, 0, 0, 256, s->W0);   // prefetch wa chunk0 during LN
    cp_commit();
    __syncthreads();                 // U visible

    // ---- 4. X = LN(X + U) ----
    ln_t(s->XT, s->S, ga, bea);
    // LN'd XT becomes visible at the pipe's first internal barrier

    // ---- 5/6. FFN: per output-half, H-half -> accF ----
    ull accF[16]; zacc16(accF);
    #pragma unroll
    for (int h = 0; h < 2; ++h) {
        zacc16(acc);
        gemm128_pipe(s->XT, wa, h * 128, 256, s->W0, s->W1, rbase, cbase, acc,
                     h == 0);
        __syncthreads();            // all warps past H-gemm; S readers (prev wb) done
        store_t(s->S, ba + h * 128, true, rbase, cbase, acc);  // H-half
        gemm128_pipe(s->S, wb + (size_t)h * 128 * DIM, 0, DIM,
                     s->W0, s->W1, rbase, cbase, accF, false);
    }
    __syncthreads();                // all done reading H (S)
    store_t(s->S, bb, false, rbase, cbase, accF);   // F
    __syncthreads();

    // ---- 7. X = LN(X + F) ----
    ln_t(s->XT, s->S, gb, beb);
    __syncthreads();
}

// ---------------- kernel 1: Kp/Vp projections + row sums ----------------
extern "C" __global__ void __launch_bounds__(NTHREADS, 3)
pre_kernel(const float* __restrict__ feat,
           const float* __restrict__ wk1, const float* __restrict__ wv1,
           const float* __restrict__ wk2, const float* __restrict__ wv2) {
    extern __shared__ char smem_raw[];
    SmemPre* s = (SmemPre*)smem_raw;
    int tid  = threadIdx.x;
    int base = blockIdx.x * BLOCK;

    #pragma unroll
    for (int i = tid; i < BLOCK * 32; i += NTHREADS) {
        int node = i >> 5;
        int k4   = (i & 31) << 2;
        int g    = base + node;
        float4 v = make_float4(0.f, 0.f, 0.f, 0.f);
        if (g < N_NODES) v = *(const float4*)(feat + (size_t)g * DIM + k4);
        s->XT[(k4 + 0) * PAD + node] = v.x;
        s->XT[(k4 + 1) * PAD + node] = v.y;
        s->XT[(k4 + 2) * PAD + node] = v.z;
        s->XT[(k4 + 3) * PAD + node] = v.w;
    }
    __syncthreads();

    {   // row sums (2 units per thread)
        #pragma unroll
        for (int u = 0; u < 2; ++u) {
            int idx  = tid + u * NTHREADS;
            int node = idx >> 3;
            int h    = idx & 7;
            float ssum = 0.f;
            #pragma unroll
            for (int i = 0; i < 16; ++i) ssum += s->XT[(h + 8 * i) * PAD + node];
            ssum += __shfl_xor_sync(0xffffffffu, ssum, 1);
            ssum += __shfl_xor_sync(0xffffffffu, ssum, 2);
            ssum += __shfl_xor_sync(0xffffffffu, ssum, 4);
            int g = base + node;
            if (h == 0 && g < N_NODES) g_rowsum[g] = ssum;
        }
    }

    int lane = tid & 31, warp = tid >> 5;
    int rbase = ((warp & 1) * 4 + (lane >> 3)) * 8;
    int cbase = (warp >> 1) * 32 + (lane & 7) * 4;
    const float* ws_in[4] = {wk1, wv1, wk2, wv2};
    float* outs[4] = {g_Kp1, g_Vp1, g_Kp2, g_Vp2};
    ull acc[16];
    #pragma unroll
    for (int w = 0; w < 4; ++w) {
        zacc16(acc);
        gemm128_pipe(s->XT, ws_in[w], 0, DIM, s->W0, s->W1, rbase, cbase, acc,
                     false);
        float* op = outs[w];
        #pragma unroll
        for (int rp = 0; rp < 4; ++rp) {
            float lo0, hi0, lo1, hi1, lo2, hi2, lo3, hi3;
            unpk(acc[0 * 4 + rp], lo0, hi0);
            unpk(acc[1 * 4 + rp], lo1, hi1);
            unpk(acc[2 * 4 + rp], lo2, hi2);
            unpk(acc[3 * 4 + rp], lo3, hi3);
            int g0 = base + rbase + rp * 2;
            if (g0 < N_NODES)
                *(float4*)(op + (size_t)g0 * DIM + cbase) = make_float4(lo0, lo1, lo2, lo3);
            if (g0 + 1 < N_NODES)
                *(float4*)(op + (size_t)(g0 + 1) * DIM + cbase) = make_float4(hi0, hi1, hi2, hi3);
        }
    }
}

// ---------------- kernel 2: fused 2-layer transformer + head ----------------
extern "C" __global__ void __launch_bounds__(NTHREADS, 2)
main_kernel(const float* __restrict__ feat,
            const int* __restrict__ nbr_idx,
            const int* __restrict__ nbr_valid,
            const float* wq1, const float* wo1, const float* bo1,
            const float* w1a, const float* b1a, const float* w1b, const float* b1b,
            const float* g1a, const float* be1a, const float* g1b, const float* be1b,
            const float* wq2, const float* wo2, const float* bo2,
            const float* w2a, const float* b2a, const float* w2b, const float* b2b,
            const float* g2a, const float* be2a, const float* g2b, const float* be2b,
            const float* w4, const float* b4,
            float* __restrict__ out) {
    extern __shared__ char smem_raw[];
    SmemMain* s = (SmemMain*)smem_raw;
    int tid  = threadIdx.x;
    int base = blockIdx.x * BLOCK;

    #pragma unroll
    for (int i = tid; i < BLOCK * 32; i += NTHREADS) {
        int node = i >> 5;
        int k4   = (i & 31) << 2;
        int g    = base + node;
        float4 v = make_float4(0.f, 0.f, 0.f, 0.f);
        if (g < N_NODES) v = *(const float4*)(feat + (size_t)g * DIM + k4);
        s->XT[(k4 + 0) * PAD + node] = v.x;
        s->XT[(k4 + 1) * PAD + node] = v.y;
        s->XT[(k4 + 2) * PAD + node] = v.z;
        s->XT[(k4 + 3) * PAD + node] = v.w;
    }
    for (int i = tid; i < BLOCK * KNBR; i += NTHREADS) {
        int node = i / KNBR;
        int j    = i - node * KNBR;
        int g    = base + node;
        int idx = 0, mflag = 1;
        if (g < N_NODES) {
            idx = nbr_idx[(size_t)g * KNBR + j];
            int valid = nbr_valid[(size_t)g * KNBR + j];   // nonzero = true
            mflag = (valid == 0) || (g_rowsum[idx] == 0.f);
        }
        s->nidx[i]  = idx;
        s->nmask[i] = mflag;
    }
    __syncthreads();

    run_layer(s, base, wq1, wo1, bo1, w1a, b1a, w1b, b1b,
              g1a, be1a, g1b, be1b, g_Kp1, g_Vp1);
    run_layer(s, base, wq2, wo2, bo2, w2a, b2a, w2b, b2b,
              g2a, be2a, g2b, be2b, g_Kp2, g_Vp2);

    // ---- head: out = tanh(X @ w4 + b4), w4: 128x64 (fits W0+W1) ----
    __syncthreads();
    {
        #pragma unroll
        for (int i = tid; i < 2048; i += NTHREADS) {   // 2048 float4
            int r  = i >> 4;
            int c4 = (i & 15) << 2;
            cp16(sptr(s->W0 + r * 64 + c4), w4 + r * 64 + c4);
        }
        cp_commit();
        cp_waitall();
    }
    __syncthreads();
    #pragma unroll
    for (int u = 0; u < 2; ++u) {
        int idx  = tid + u * NTHREADS;
        int node = idx >> 3;
        int c0   = (idx & 7) * 8;
        float acc8[8];
        #pragma unroll
        for (int c = 0; c < 8; ++c) acc8[c] = 0.f;
        #pragma unroll 4
        for (int kk = 0; kk < DIM; ++kk) {
            float a = s->XT[kk * PAD + node];
            float4 w0 = *(const float4*)(s->W0 + kk * 64 + c0);
            float4 w1 = *(const float4*)(s->W0 + kk * 64 + c0 + 4);
            acc8[0] = fmaf(a, w0.x, acc8[0]);
            acc8[1] = fmaf(a, w0.y, acc8[1]);
            acc8[2] = fmaf(a, w0.z, acc8[2]);
            acc8[3] = fmaf(a, w0.w, acc8[3]);
            acc8[4] = fmaf(a, w1.x, acc8[4]);
            acc8[5] = fmaf(a, w1.y, acc8[5]);
            acc8[6] = fmaf(a, w1.z, acc8[6]);
            acc8[7] = fmaf(a, w1.w, acc8[7]);
        }
        int g = base + node;
        if (g < N_NODES) {
            #pragma unroll
            for (int c = 0; c < 8; ++c)
                out[(size_t)g * 64 + c0 + c] = tanhf(acc8[c] + b4[c0 + c]);
        }
    }
}

// ---------------- host launch ----------------
extern "C" void kernel_launch(void* const* d_in, const int* in_sizes, int n_in,
                              void* d_out, int out_size) {
    const float* feat  = (const float*)d_in[0];
    const int* nbr_idx = (const int*)d_in[1];
    const int* nbr_val = (const int*)d_in[2];
    const float* wq1 = (const float*)d_in[3];
    const float* wk1 = (const float*)d_in[4];
    const float* wv1 = (const float*)d_in[5];
    const float* wo1 = (const float*)d_in[6];
    const float* bo1 = (const float*)d_in[7];
    const float* w1a = (const float*)d_in[8];
    const float* b1a = (const float*)d_in[9];
    const float* w1b = (const float*)d_in[10];
    const float* b1b = (const float*)d_in[11];
    const float* g1a = (const float*)d_in[12];
    const float* be1a = (const float*)d_in[13];
    const float* g1b = (const float*)d_in[14];
    const float* be1b = (const float*)d_in[15];
    const float* wq2 = (const float*)d_in[16];
    const float* wk2 = (const float*)d_in[17];
    const float* wv2 = (const float*)d_in[18];
    const float* wo2 = (const float*)d_in[19];
    const float* bo2 = (const float*)d_in[20];
    const float* w2a = (const float*)d_in[21];
    const float* b2a = (const float*)d_in[22];
    const float* w2b = (const float*)d_in[23];
    const float* b2b = (const float*)d_in[24];
    const float* g2a = (const float*)d_in[25];
    const float* be2a = (const float*)d_in[26];
    const float* g2b = (const float*)d_in[27];
    const float* be2b = (const float*)d_in[28];
    const float* w4 = (const float*)d_in[29];
    const float* b4 = (const float*)d_in[30];
    float* out = (float*)d_out;

    size_t smem_pre  = sizeof(SmemPre);
    size_t smem_main = sizeof(SmemMain);
    cudaFuncSetAttribute(pre_kernel,  cudaFuncAttributeMaxDynamicSharedMemorySize, (int)smem_pre);
    cudaFuncSetAttribute(main_kernel, cudaFuncAttributeMaxDynamicSharedMemorySize, (int)smem_main);

    pre_kernel<<<NTILES, NTHREADS, smem_pre>>>(feat, wk1, wv1, wk2, wv2);
    main_kernel<<<NTILES, NTHREADS, smem_main>>>(
        feat, nbr_idx, nbr_val,
        wq1, wo1, bo1, w1a, b1a, w1b, b1b, g1a, be1a, g1b, be1b,
        wq2, wo2, bo2, w2a, b2a, w2b, b2b, g2a, be2a, g2b, be2b,
        w4, b4, out);
}